// round 14
// baseline (speedup 1.0000x reference)
#include <cuda_runtime.h>
#include <cuda_fp16.h>
#include <cstdint>

// Problem sizes (fixed by setup_inputs)
#define NN 8192   // nodes
#define DD 128    // embedding dim
#define EE 4096   // hyperedges
#define KK 8192   // reduction dim of the big GEMMs
#define LN_EPS 1e-5f

#define NTILE 64
#define STAGES 4
#define KT 64                           // k per iter
#define SK_IT (KK / KT / 2)             // 64 iters per split-K half

// layer GEMMs: A 16KB + B 8KB per stage = 24KB; 4 stages = 96KB (2 CTAs/SM)
#define A_BYTES 16384
#define B_BYTES 8192
#define STG (A_BYTES + B_BYTES)
#define SK_SMEM (STAGES * STG)          // 98304

// hcv kernel: A pool 64KB | B32 pool 64KB | B16 8KB
#define CV_A_OFF 0
#define CV_B32_OFF (4 * 16384)
#define CV_B16_OFF (8 * 16384)
#define HCV_SMEM (CV_B16_OFF + 8192)    // 139264

// ---------------- scratch (device globals; no allocation allowed) ------------
__device__ __half g_Th [(size_t)NN * NN];     // T fp16             128 MB
__device__ __half g_Xh [(size_t)DD * NN];     // x^T fp16             2 MB
__device__ __half g_Tbh[(size_t)DD * NN];     // t^T fp16             2 MB
__device__ float  g_P  [(size_t)2 * DD * NN]; // split-K partials     8 MB
__device__ float  g_S  [(size_t)2 * DD * EE]; // final partials       4 MB
__device__ float  g_counts[EE];

// ---------------- helpers ----------------
__device__ __forceinline__ uint32_t h2u(__half2 h) {
  uint32_t u;
  *reinterpret_cast<__half2*>(&u) = h;
  return u;
}
__device__ __forceinline__ uint32_t smem_u32(const void* p) {
  uint32_t a;
  asm("{ .reg .u64 t; cvta.to.shared.u64 t, %1; cvt.u32.u64 %0, t; }" : "=r"(a) : "l"(p));
  return a;
}
__device__ __forceinline__ uint32_t swz(uint32_t b) { return b ^ ((b >> 3) & 0x70); }
__device__ __forceinline__ void cp_async16(uint32_t dst, const void* src) {
  asm volatile("cp.async.cg.shared.global [%0], [%1], 16;" :: "r"(dst), "l"(src));
}
__device__ __forceinline__ void ldmatrix_x4(uint32_t& r0, uint32_t& r1, uint32_t& r2,
                                            uint32_t& r3, uint32_t addr) {
  asm volatile("ldmatrix.sync.aligned.m8n8.x4.shared.b16 {%0,%1,%2,%3}, [%4];"
               : "=r"(r0), "=r"(r1), "=r"(r2), "=r"(r3) : "r"(addr));
}
__device__ __forceinline__ void ldmatrix_x4t(uint32_t& r0, uint32_t& r1, uint32_t& r2,
                                             uint32_t& r3, uint32_t addr) {
  asm volatile("ldmatrix.sync.aligned.m8n8.x4.trans.shared.b16 {%0,%1,%2,%3}, [%4];"
               : "=r"(r0), "=r"(r1), "=r"(r2), "=r"(r3) : "r"(addr));
}
__device__ __forceinline__ void mma16816(float* c, uint32_t a0, uint32_t a1, uint32_t a2,
                                         uint32_t a3, uint32_t b0, uint32_t b1) {
  asm volatile(
      "mma.sync.aligned.m16n8k16.row.col.f32.f16.f16.f32 "
      "{%0,%1,%2,%3}, {%4,%5,%6,%7}, {%8,%9}, {%0,%1,%2,%3};"
      : "+f"(c[0]), "+f"(c[1]), "+f"(c[2]), "+f"(c[3])
      : "r"(a0), "r"(a1), "r"(a2), "r"(a3), "r"(b0), "r"(b1));
}

// ==== GEMM NT split-K: P[by][128,ntile] = A[128,Khalf] @ B[ntile,Khalf]^T ====
__global__ __launch_bounds__(256, 2)
void gemm_nt_sk(const __half* __restrict__ A, const __half* __restrict__ B,
                float* __restrict__ P) {
  extern __shared__ char smem[];
  uint32_t sb = smem_u32(smem);
  const int tid = threadIdx.x;
  const int wid = tid >> 5, lane = tid & 31;
  const int n0 = blockIdx.x * NTILE;
  const int kOff = blockIdx.y * SK_IT;
  const int wm = (wid & 3) * 32;
  const int wn = (wid >> 2) * 32;

  const int lj = lane >> 3, lr = lane & 7;
  int aRow[2], bRow[2];
  aRow[0] = wm + ((lj & 1) << 3) + lr;
  aRow[1] = aRow[0] + 16;
  const int aChO = lj >> 1;
  bRow[0] = wn + ((lj >> 1) << 3) + lr;
  bRow[1] = bRow[0] + 16;
  const int bChO = lj & 1;

  float acc[2][4][4];
#pragma unroll
  for (int i = 0; i < 2; i++)
#pragma unroll
    for (int j = 0; j < 4; j++)
#pragma unroll
      for (int q = 0; q < 4; q++) acc[i][j][q] = 0.f;

  auto load_stage = [&](int s, int kc) {
    uint32_t base = sb + s * STG;
    const __half* Ak = A + (size_t)kc * KT;
    const __half* Bk = B + (size_t)n0 * KK + (size_t)kc * KT;
#pragma unroll
    for (int j = 0; j < 6; j++) {
      int idx = tid + j * 256;
      int c = idx & 7;
      if (idx < 1024) {
        int row = idx >> 3;
        cp_async16(base + swz(row * 128 + c * 16), Ak + (size_t)row * KK + c * 8);
      } else {
        int row = (idx - 1024) >> 3;
        cp_async16(base + A_BYTES + swz(row * 128 + c * 16),
                   Bk + (size_t)row * KK + c * 8);
      }
    }
  };

  auto compute_stage = [&](int s) {
    uint32_t abase = sb + s * STG;
    uint32_t bbase = abase + A_BYTES;
#pragma unroll
    for (int ks = 0; ks < 4; ks++) {
      const int kc2 = ks * 2;
      uint32_t a[2][4], b[2][4];
#pragma unroll
      for (int mt = 0; mt < 2; mt++) {
        uint32_t addr = abase + aRow[mt] * 128 + (((kc2 + aChO) ^ (aRow[mt] & 7)) << 4);
        ldmatrix_x4(a[mt][0], a[mt][1], a[mt][2], a[mt][3], addr);
      }
#pragma unroll
      for (int p = 0; p < 2; p++) {
        uint32_t addr = bbase + bRow[p] * 128 + (((kc2 + bChO) ^ (bRow[p] & 7)) << 4);
        ldmatrix_x4(b[p][0], b[p][1], b[p][2], b[p][3], addr);
      }
#pragma unroll
      for (int mt = 0; mt < 2; mt++)
#pragma unroll
        for (int nt = 0; nt < 4; nt++) {
          uint32_t b0 = b[nt >> 1][(nt & 1) ? 2 : 0];
          uint32_t b1 = b[nt >> 1][(nt & 1) ? 3 : 1];
          mma16816(acc[mt][nt], a[mt][0], a[mt][1], a[mt][2], a[mt][3], b0, b1);
        }
    }
  };

#pragma unroll
  for (int s = 0; s < STAGES - 1; s++) {
    load_stage(s, kOff + s);
    asm volatile("cp.async.commit_group;" ::: "memory");
  }
  for (int it = 0; it < SK_IT; ++it) {
    int s = it & (STAGES - 1);
    asm volatile("cp.async.wait_group %0;" :: "n"(STAGES - 2) : "memory");
    __syncthreads();
    int pf = it + STAGES - 1;
    if (pf < SK_IT) load_stage(pf & (STAGES - 1), kOff + pf);
    asm volatile("cp.async.commit_group;" ::: "memory");
    compute_stage(s);
  }

  float* C = P + (size_t)blockIdx.y * DD * NN;
  const int g = lane >> 2, tg = lane & 3;
#pragma unroll
  for (int mt = 0; mt < 2; mt++)
#pragma unroll
    for (int nt = 0; nt < 4; nt++) {
      int row0 = wm + mt * 16 + g;
      int col0 = n0 + wn + nt * 8 + tg * 2;
      *(float2*)(C + (size_t)row0 * NN + col0) =
          make_float2(acc[mt][nt][0], acc[mt][nt][1]);
      *(float2*)(C + (size_t)(row0 + 8) * NN + col0) =
          make_float2(acc[mt][nt][2], acc[mt][nt][3]);
    }
}

// ==== GEMM TN split-K: P[by][128,ntile] = A[128,Khalf] @ B[Khalf,ntile] ======
__global__ __launch_bounds__(256, 2)
void gemm_tn_sk(const __half* __restrict__ A, const __half* __restrict__ B, int ldB,
                float* __restrict__ P) {
  extern __shared__ char smem[];
  uint32_t sb = smem_u32(smem);
  const int tid = threadIdx.x;
  const int wid = tid >> 5, lane = tid & 31;
  const int n0 = blockIdx.x * NTILE;
  const int kOff = blockIdx.y * SK_IT;
  const int wm = (wid & 3) * 32;
  const int wn = (wid >> 2) * 32;

  const int lj = lane >> 3, lr = lane & 7;
  int aRow[2];
  aRow[0] = wm + ((lj & 1) << 3) + lr;
  aRow[1] = aRow[0] + 16;
  const int aChO = lj >> 1;
  const int bKsub = ((lj & 1) << 3) + lr;
  const int bChSub = (wn >> 3) + (lj >> 1);

  float acc[2][4][4];
#pragma unroll
  for (int i = 0; i < 2; i++)
#pragma unroll
    for (int j = 0; j < 4; j++)
#pragma unroll
      for (int q = 0; q < 4; q++) acc[i][j][q] = 0.f;

  auto load_stage = [&](int s, int kc) {
    uint32_t base = sb + s * STG;
    const __half* Ak = A + (size_t)kc * KT;
    const __half* Bk = B + (size_t)kc * KT * ldB + n0;
#pragma unroll
    for (int j = 0; j < 6; j++) {
      int idx = tid + j * 256;
      int c = idx & 7;
      if (idx < 1024) {
        int row = idx >> 3;
        cp_async16(base + swz(row * 128 + c * 16), Ak + (size_t)row * KK + c * 8);
      } else {
        int row = (idx - 1024) >> 3;
        cp_async16(base + A_BYTES + swz(row * 128 + c * 16),
                   Bk + (size_t)row * ldB + c * 8);
      }
    }
  };

  auto compute_stage = [&](int s) {
    uint32_t abase = sb + s * STG;
    uint32_t bbase = abase + A_BYTES;
#pragma unroll
    for (int ks = 0; ks < 4; ks++) {
      const int kc2 = ks * 2;
      uint32_t a[2][4], b[2][4];
#pragma unroll
      for (int mt = 0; mt < 2; mt++) {
        uint32_t addr = abase + aRow[mt] * 128 + (((kc2 + aChO) ^ (aRow[mt] & 7)) << 4);
        ldmatrix_x4(a[mt][0], a[mt][1], a[mt][2], a[mt][3], addr);
      }
      int krow = ks * 16 + bKsub;
#pragma unroll
      for (int p = 0; p < 2; p++) {
        int chunk = bChSub + p * 2;
        uint32_t addr = bbase + krow * 128 + ((chunk ^ (krow & 7)) << 4);
        ldmatrix_x4t(b[p][0], b[p][1], b[p][2], b[p][3], addr);
      }
#pragma unroll
      for (int mt = 0; mt < 2; mt++)
#pragma unroll
        for (int nt = 0; nt < 4; nt++) {
          uint32_t b0 = b[nt >> 1][(nt & 1) << 1];
          uint32_t b1 = b[nt >> 1][((nt & 1) << 1) + 1];
          mma16816(acc[mt][nt], a[mt][0], a[mt][1], a[mt][2], a[mt][3], b0, b1);
        }
    }
  };

#pragma unroll
  for (int s = 0; s < STAGES - 1; s++) {
    load_stage(s, kOff + s);
    asm volatile("cp.async.commit_group;" ::: "memory");
  }
  for (int it = 0; it < SK_IT; ++it) {
    int s = it & (STAGES - 1);
    asm volatile("cp.async.wait_group %0;" :: "n"(STAGES - 2) : "memory");
    __syncthreads();
    int pf = it + STAGES - 1;
    if (pf < SK_IT) load_stage(pf & (STAGES - 1), kOff + pf);
    asm volatile("cp.async.commit_group;" ::: "memory");
    compute_stage(s);
  }

  float* C = P + (size_t)blockIdx.y * DD * NN;
  const int g = lane >> 2, tg = lane & 3;
#pragma unroll
  for (int mt = 0; mt < 2; mt++)
#pragma unroll
    for (int nt = 0; nt < 4; nt++) {
      int row0 = wm + mt * 16 + g;
      int col0 = n0 + wn + nt * 8 + tg * 2;
      *(float2*)(C + (size_t)row0 * NN + col0) =
          make_float2(acc[mt][nt][0], acc[mt][nt][1]);
      *(float2*)(C + (size_t)(row0 + 8) * NN + col0) =
          make_float2(acc[mt][nt][2], acc[mt][nt][3]);
    }
}

// ---------------- combine kernels ----------------
// Tbh = fp16(P0 + P1)
__global__ void k_comb_h(const float* __restrict__ P, __half* __restrict__ Out) {
  size_t i = ((size_t)blockIdx.x * 256 + threadIdx.x) * 8;
  const float4 a0 = *(const float4*)(P + i);
  const float4 a1 = *(const float4*)(P + i + 4);
  const float4 b0 = *(const float4*)(P + (size_t)DD * NN + i);
  const float4 b1 = *(const float4*)(P + (size_t)DD * NN + i + 4);
  uint4 o;
  o.x = h2u(__floats2half2_rn(a0.x + b0.x, a0.y + b0.y));
  o.y = h2u(__floats2half2_rn(a0.z + b0.z, a0.w + b0.w));
  o.z = h2u(__floats2half2_rn(a1.x + b1.x, a1.y + b1.y));
  o.w = h2u(__floats2half2_rn(a1.z + b1.z, a1.w + b1.w));
  *(uint4*)(Out + i) = o;
}

// Xh = LN_cols(P0 + P1) over the 128 rows
__global__ void k_comb_ln(const float* __restrict__ P, const float* __restrict__ gam,
                          const float* __restrict__ bet, __half* __restrict__ Xh) {
  __shared__ float sg[DD], sb2[DD];
  if (threadIdx.x < DD) {
    sg[threadIdx.x] = gam[threadIdx.x];
    sb2[threadIdx.x] = bet[threadIdx.x];
  }
  __syncthreads();
  int j = blockIdx.x * blockDim.x + threadIdx.x;
  const float* P1 = P + (size_t)DD * NN;
  float s = 0.f, sq = 0.f;
#pragma unroll 8
  for (int d = 0; d < DD; ++d) {
    float v = P[(size_t)d * NN + j] + P1[(size_t)d * NN + j];
    s += v; sq += v * v;
  }
  float mean = s * (1.0f / DD);
  float var = sq * (1.0f / DD) - mean * mean;
  float r = rsqrtf(var + LN_EPS);
#pragma unroll 8
  for (int d = 0; d < DD; ++d) {
    float v = P[(size_t)d * NN + j] + P1[(size_t)d * NN + j];
    Xh[(size_t)d * NN + j] = __float2half((v - mean) * r * sg[d] + sb2[d]);
  }
}

// ===== Final GEMM with fused h conversion + counts (unchanged champion) ======
__global__ __launch_bounds__(256, 1)
void gemm_tn_hcv(const __half* __restrict__ A, const int* __restrict__ H,
                 int kIters, float* __restrict__ Cp, int ldC,
                 float* __restrict__ counts) {
  extern __shared__ char smem[];
  uint32_t sb = smem_u32(smem);
  const int tid = threadIdx.x;
  const int wid = tid >> 5, lane = tid & 31;
  const int n0 = blockIdx.x * NTILE;
  const int kOff = blockIdx.y * kIters;
  const int wm = (wid & 3) * 32;
  const int wn = (wid >> 2) * 32;

  const int lj = lane >> 3, lr = lane & 7;
  int aRow[2];
  aRow[0] = wm + ((lj & 1) << 3) + lr;
  aRow[1] = aRow[0] + 16;
  const int aChO = lj >> 1;
  const int bKsub = ((lj & 1) << 3) + lr;
  const int bChSub = (wn >> 3) + (lj >> 1);

  float acc[2][4][4];
#pragma unroll
  for (int i = 0; i < 2; i++)
#pragma unroll
    for (int j = 0; j < 4; j++)
#pragma unroll
      for (int q = 0; q < 4; q++) acc[i][j][q] = 0.f;

  float cnt[16];
#pragma unroll
  for (int j = 0; j < 16; j++) cnt[j] = 0.f;

  auto load_stage = [&](int s, int kc) {
    const __half* Ak = A + (size_t)kc * KT;
    const int* Hk = H + (size_t)kc * KT * EE + n0;
#pragma unroll
    for (int j = 0; j < 4; j++) {
      int idx = tid + j * 256;
      int c = idx & 7, row = idx >> 3;
      cp_async16(sb + CV_A_OFF + s * 16384 + swz(row * 128 + c * 16),
                 Ak + (size_t)row * KK + c * 8);
    }
#pragma unroll
    for (int j = 0; j < 4; j++) {
      int idx = tid + j * 256;
      int c = idx & 15, row = idx >> 4;
      cp_async16(sb + CV_B32_OFF + s * 16384 + row * 256 + c * 16,
                 Hk + (size_t)row * EE + c * 4);
    }
  };

#pragma unroll
  for (int s = 0; s < STAGES - 1; s++) {
    load_stage(s, kOff + s);
    asm volatile("cp.async.commit_group;" ::: "memory");
  }
  const int cR = tid >> 2, cQ = tid & 3;
  for (int it = 0; it < kIters; ++it) {
    int s = it & (STAGES - 1);
    asm volatile("cp.async.wait_group %0;" :: "n"(STAGES - 2) : "memory");
    __syncthreads();
    {
      const int4* p = (const int4*)(smem + CV_B32_OFF + s * 16384 + cR * 256 + cQ * 64);
      int4 v0 = p[0], v1 = p[1], v2 = p[2], v3 = p[3];
      float f[16];
      f[0] = (v0.x > 0) ? 1.f : 0.f;  f[1] = (v0.y > 0) ? 1.f : 0.f;
      f[2] = (v0.z > 0) ? 1.f : 0.f;  f[3] = (v0.w > 0) ? 1.f : 0.f;
      f[4] = (v1.x > 0) ? 1.f : 0.f;  f[5] = (v1.y > 0) ? 1.f : 0.f;
      f[6] = (v1.z > 0) ? 1.f : 0.f;  f[7] = (v1.w > 0) ? 1.f : 0.f;
      f[8] = (v2.x > 0) ? 1.f : 0.f;  f[9] = (v2.y > 0) ? 1.f : 0.f;
      f[10] = (v2.z > 0) ? 1.f : 0.f; f[11] = (v2.w > 0) ? 1.f : 0.f;
      f[12] = (v3.x > 0) ? 1.f : 0.f; f[13] = (v3.y > 0) ? 1.f : 0.f;
      f[14] = (v3.z > 0) ? 1.f : 0.f; f[15] = (v3.w > 0) ? 1.f : 0.f;
#pragma unroll
      for (int j = 0; j < 16; j++) cnt[j] += f[j];
      uint4 u0, u1;
      u0.x = h2u(__floats2half2_rn(f[0], f[1]));
      u0.y = h2u(__floats2half2_rn(f[2], f[3]));
      u0.z = h2u(__floats2half2_rn(f[4], f[5]));
      u0.w = h2u(__floats2half2_rn(f[6], f[7]));
      u1.x = h2u(__floats2half2_rn(f[8], f[9]));
      u1.y = h2u(__floats2half2_rn(f[10], f[11]));
      u1.z = h2u(__floats2half2_rn(f[12], f[13]));
      u1.w = h2u(__floats2half2_rn(f[14], f[15]));
      *(uint4*)(smem + CV_B16_OFF + swz(cR * 128 + cQ * 32)) = u0;
      *(uint4*)(smem + CV_B16_OFF + swz(cR * 128 + cQ * 32 + 16)) = u1;
    }
    int pf = it + STAGES - 1;
    if (pf < kIters) load_stage(pf & (STAGES - 1), kOff + pf);
    asm volatile("cp.async.commit_group;" ::: "memory");
    __syncthreads();
    {
      uint32_t abase = sb + CV_A_OFF + s * 16384;
      uint32_t bbase = sb + CV_B16_OFF;
#pragma unroll
      for (int ks = 0; ks < 4; ks++) {
        const int kc2 = ks * 2;
        uint32_t a[2][4], b[2][4];
#pragma unroll
        for (int mt = 0; mt < 2; mt++) {
          uint32_t addr = abase + aRow[mt] * 128 + (((kc2 + aChO) ^ (aRow[mt] & 7)) << 4);
          ldmatrix_x4(a[mt][0], a[mt][1], a[mt][2], a[mt][3], addr);
        }
        int krow = ks * 16 + bKsub;
#pragma unroll
        for (int p = 0; p < 2; p++) {
          int chunk = bChSub + p * 2;
          uint32_t addr = bbase + krow * 128 + ((chunk ^ (krow & 7)) << 4);
          ldmatrix_x4t(b[p][0], b[p][1], b[p][2], b[p][3], addr);
        }
#pragma unroll
        for (int mt = 0; mt < 2; mt++)
#pragma unroll
          for (int nt = 0; nt < 4; nt++) {
            uint32_t b0 = b[nt >> 1][(nt & 1) << 1];
            uint32_t b1 = b[nt >> 1][((nt & 1) << 1) + 1];
            mma16816(acc[mt][nt], a[mt][0], a[mt][1], a[mt][2], a[mt][3], b0, b1);
          }
      }
    }
  }

  float* C = Cp + (size_t)blockIdx.y * DD * EE;
  const int g = lane >> 2, tg = lane & 3;
#pragma unroll
  for (int mt = 0; mt < 2; mt++)
#pragma unroll
    for (int nt = 0; nt < 4; nt++) {
      int row0 = wm + mt * 16 + g;
      int col0 = n0 + wn + nt * 8 + tg * 2;
      *(float2*)(C + (size_t)row0 * ldC + col0) =
          make_float2(acc[mt][nt][0], acc[mt][nt][1]);
      *(float2*)(C + (size_t)(row0 + 8) * ldC + col0) =
          make_float2(acc[mt][nt][2], acc[mt][nt][3]);
    }

#pragma unroll
  for (int j = 0; j < 16; j++) {
#pragma unroll
    for (int o = 4; o < 32; o <<= 1)
      cnt[j] += __shfl_xor_sync(0xffffffffu, cnt[j], o);
  }
  if (lane < 4) {
#pragma unroll
    for (int j = 0; j < 16; j++)
      atomicAdd(&counts[n0 + cQ * 16 + j], cnt[j]);
  }
}

// ---------------- conversion / aux kernels ----------------
__global__ void k_convT(const float* __restrict__ T, __half* __restrict__ Th) {
  size_t i = (size_t)blockIdx.x * blockDim.x + threadIdx.x;
  size_t n8 = (size_t)NN * NN / 8;
  const float4* src = (const float4*)T;
  uint4* dst = (uint4*)Th;
  for (size_t j = i; j < n8; j += (size_t)gridDim.x * blockDim.x) {
    float4 a = src[2 * j], b = src[2 * j + 1];
    uint4 o;
    o.x = h2u(__floats2half2_rn(a.x, a.y));
    o.y = h2u(__floats2half2_rn(a.z, a.w));
    o.z = h2u(__floats2half2_rn(b.x, b.y));
    o.w = h2u(__floats2half2_rn(b.z, b.w));
    dst[j] = o;
  }
}

// x0 transpose->fp16 with counts zeroing folded in
__global__ void k_conv_x0(const float* __restrict__ x0, __half* __restrict__ Xh,
                          float* __restrict__ counts) {
  __shared__ float t[32][33];
  int d0 = blockIdx.x << 5, n0 = blockIdx.y << 5;
  int x = threadIdx.x, y = threadIdx.y;
  if (blockIdx.x == 0) {
    int ft = y * 32 + x;
    for (int i = blockIdx.y * 256 + ft; i < EE; i += 256 * (NN / 32)) counts[i] = 0.f;
  }
#pragma unroll
  for (int i = 0; i < 32; i += 8)
    t[y + i][x] = x0[(size_t)(n0 + y + i) * DD + d0 + x];
  __syncthreads();
#pragma unroll
  for (int i = 0; i < 32; i += 8)
    Xh[(size_t)(d0 + y + i) * NN + n0 + x] = __float2half(t[x][y + i]);
}

__global__ void k_final_max(const float* __restrict__ S, const float* __restrict__ counts,
                            float* __restrict__ out) {
  int d = blockIdx.x;
  const float* S0 = S + (size_t)d * EE;
  const float* S1 = S + (size_t)DD * EE + (size_t)d * EE;
  float m = -3.402823466e38f;
  for (int e = threadIdx.x; e < EE; e += blockDim.x)
    m = fmaxf(m, (S0[e] + S1[e]) / counts[e]);
#pragma unroll
  for (int o = 16; o > 0; o >>= 1) m = fmaxf(m, __shfl_xor_sync(0xffffffffu, m, o));
  __shared__ float red[4];
  int lane = threadIdx.x & 31, w = threadIdx.x >> 5;
  if (lane == 0) red[w] = m;
  __syncthreads();
  if (threadIdx.x == 0)
    out[d] = fmaxf(fmaxf(red[0], red[1]), fmaxf(red[2], red[3]));
}

// ---------------- launch ----------------
extern "C" void kernel_launch(void* const* d_in, const int* in_sizes, int n_in,
                              void* d_out, int out_size) {
  const float* x0  = (const float*)d_in[0];  // [8192,128]
  const float* T   = (const float*)d_in[1];  // [8192,8192]
  const float* gam = (const float*)d_in[2];  // [128]
  const float* bet = (const float*)d_in[3];  // [128]
  const int*   h   = (const int*)d_in[4];    // [8192,4096]
  float* out = (float*)d_out;                // [128]

  __half *Th, *Xh, *Tbh;
  float *P, *S, *counts;
  cudaGetSymbolAddress((void**)&Th,  g_Th);
  cudaGetSymbolAddress((void**)&Xh,  g_Xh);
  cudaGetSymbolAddress((void**)&Tbh, g_Tbh);
  cudaGetSymbolAddress((void**)&P,   g_P);
  cudaGetSymbolAddress((void**)&S,   g_S);
  cudaGetSymbolAddress((void**)&counts, g_counts);

  cudaFuncSetAttribute(gemm_nt_sk, cudaFuncAttributeMaxDynamicSharedMemorySize, SK_SMEM);
  cudaFuncSetAttribute(gemm_tn_sk, cudaFuncAttributeMaxDynamicSharedMemorySize, SK_SMEM);
  cudaFuncSetAttribute(gemm_tn_hcv, cudaFuncAttributeMaxDynamicSharedMemorySize, HCV_SMEM);

  k_conv_x0<<<dim3(DD / 32, NN / 32), dim3(32, 8)>>>(x0, Xh, counts);
  k_convT<<<1184, 256>>>(T, Th);

  for (int l = 0; l < 3; ++l) {  // num_layers fixed at 3 by setup_inputs
    gemm_nt_sk<<<dim3(NN / NTILE, 2), 256, SK_SMEM>>>(Xh, Th, P);
    k_comb_h<<<(int)((size_t)DD * NN / 2048), 256>>>(P, Tbh);
    gemm_tn_sk<<<dim3(NN / NTILE, 2), 256, SK_SMEM>>>(Tbh, Th, NN, P);
    k_comb_ln<<<NN / 256, 256>>>(P, gam, bet, Xh);
  }
  // final: sums^T = x^T @ float(h>0), h converted in-kernel, split-K=2
  gemm_tn_hcv<<<dim3(EE / NTILE, 2), 256, HCV_SMEM>>>(Xh, h, (KK / KT) / 2, S, EE, counts);
  k_final_max<<<DD, 128>>>(S, counts, out);
}

// round 15
// speedup vs baseline: 1.0388x; 1.0388x over previous
#include <cuda_runtime.h>
#include <cuda_fp16.h>
#include <cstdint>

// Problem sizes (fixed by setup_inputs)
#define NN 8192   // nodes
#define DD 128    // embedding dim
#define EE 4096   // hyperedges
#define KK 8192   // reduction dim of the big GEMMs
#define LN_EPS 1e-5f

// ---------------- GEMM config: 128x64 tile, KTILE=128 (2 swizzle panels) -----
#define KTILE 128                      // halfs per k-chunk = 2 x 128B panels
#define NTILE 64
#define STAGES 4
#define NIT (KK / KTILE)               // 64 k-iterations
#define A_STAGE_BYTES (2 * 16384)      // 32 KB: 2 panels (128 rows x 128B)
#define B_STAGE_BYTES (2 * 8192)       // 16 KB: 2 panels (64 rows x 128B)
#define STAGE_BYTES (A_STAGE_BYTES + B_STAGE_BYTES)   // 48 KB
#define GEMM_SMEM (STAGES * STAGE_BYTES)              // 192 KB

// hcv kernel (KTILE=64): A pool 64KB | B32 pool 64KB | B16 8KB
#define HKT 64
#define CV_A_OFF 0
#define CV_B32_OFF (4 * 16384)
#define CV_B16_OFF (8 * 16384)
#define HCV_SMEM (CV_B16_OFF + 8192)   // 139264 B

// ---------------- scratch (device globals; no allocation allowed) ------------
__device__ __half g_Th [(size_t)NN * NN];     // T fp16             128 MB
__device__ __half g_Xh [(size_t)DD * NN];     // x^T fp16             2 MB
__device__ __half g_Tbh[(size_t)DD * NN];     // t^T fp16             2 MB
__device__ float  g_S  [(size_t)2 * DD * EE]; // final partials       4 MB
__device__ float  g_counts[EE];

// ---------------- helpers ----------------
__device__ __forceinline__ uint32_t h2u(__half2 h) {
  uint32_t u;
  *reinterpret_cast<__half2*>(&u) = h;
  return u;
}
__device__ __forceinline__ uint32_t smem_u32(const void* p) {
  uint32_t a;
  asm("{ .reg .u64 t; cvta.to.shared.u64 t, %1; cvt.u32.u64 %0, t; }" : "=r"(a) : "l"(p));
  return a;
}
__device__ __forceinline__ uint32_t swz(uint32_t b) { return b ^ ((b >> 3) & 0x70); }
__device__ __forceinline__ void cp_async16(uint32_t dst, const void* src) {
  asm volatile("cp.async.cg.shared.global [%0], [%1], 16;" :: "r"(dst), "l"(src));
}
__device__ __forceinline__ void ldmatrix_x4(uint32_t& r0, uint32_t& r1, uint32_t& r2,
                                            uint32_t& r3, uint32_t addr) {
  asm volatile("ldmatrix.sync.aligned.m8n8.x4.shared.b16 {%0,%1,%2,%3}, [%4];"
               : "=r"(r0), "=r"(r1), "=r"(r2), "=r"(r3) : "r"(addr));
}
__device__ __forceinline__ void ldmatrix_x4t(uint32_t& r0, uint32_t& r1, uint32_t& r2,
                                             uint32_t& r3, uint32_t addr) {
  asm volatile("ldmatrix.sync.aligned.m8n8.x4.trans.shared.b16 {%0,%1,%2,%3}, [%4];"
               : "=r"(r0), "=r"(r1), "=r"(r2), "=r"(r3) : "r"(addr));
}
__device__ __forceinline__ void mma16816(float* c, uint32_t a0, uint32_t a1, uint32_t a2,
                                         uint32_t a3, uint32_t b0, uint32_t b1) {
  asm volatile(
      "mma.sync.aligned.m16n8k16.row.col.f32.f16.f16.f32 "
      "{%0,%1,%2,%3}, {%4,%5,%6,%7}, {%8,%9}, {%0,%1,%2,%3};"
      : "+f"(c[0]), "+f"(c[1]), "+f"(c[2]), "+f"(c[3])
      : "r"(a0), "r"(a1), "r"(a2), "r"(a3), "r"(b0), "r"(b1));
}

// ============ GEMM 1: C[128,Ntot] = A[128,K] @ B[Ntot,K]^T, B K-major =========
__global__ __launch_bounds__(256, 1)
void gemm_nt(const __half* __restrict__ A, const __half* __restrict__ B,
             __half* __restrict__ C, int ldC) {
  extern __shared__ char smem[];
  uint32_t sb = smem_u32(smem);
  const int tid = threadIdx.x;
  const int wid = tid >> 5, lane = tid & 31;
  const int n0 = blockIdx.x * NTILE;
  const int wm = (wid & 3) * 32;
  const int wn = (wid >> 2) * 32;

  const int lj = lane >> 3, lr = lane & 7;
  int aRow[2], bRow[2];
  aRow[0] = wm + ((lj & 1) << 3) + lr;
  aRow[1] = aRow[0] + 16;
  const int aChO = lj >> 1;
  bRow[0] = wn + ((lj >> 1) << 3) + lr;
  bRow[1] = bRow[0] + 16;
  const int bChO = lj & 1;

  float acc[2][4][4];
#pragma unroll
  for (int i = 0; i < 2; i++)
#pragma unroll
    for (int j = 0; j < 4; j++)
#pragma unroll
      for (int q = 0; q < 4; q++) acc[i][j][q] = 0.f;

  auto load_stage = [&](int s, int kc) {
    uint32_t base = sb + s * STAGE_BYTES;
    const __half* Ak = A + (size_t)kc * KTILE;
    const __half* Bk = B + (size_t)n0 * KK + (size_t)kc * KTILE;
#pragma unroll
    for (int j = 0; j < 8; j++) {
      int idx = tid + j * 256;
      int c = idx & 15, row = idx >> 4;
      int panel = c >> 3, pc = c & 7;
      cp_async16(base + panel * 16384 + swz(row * 128 + pc * 16),
                 Ak + (size_t)row * KK + c * 8);
    }
#pragma unroll
    for (int j = 0; j < 4; j++) {
      int idx = tid + j * 256;
      int c = idx & 15, row = idx >> 4;
      int panel = c >> 3, pc = c & 7;
      cp_async16(base + A_STAGE_BYTES + panel * 8192 + swz(row * 128 + pc * 16),
                 Bk + (size_t)row * KK + c * 8);
    }
  };

  auto compute_stage = [&](int s) {
    uint32_t abase = sb + s * STAGE_BYTES;
    uint32_t bbase = abase + A_STAGE_BYTES;
#pragma unroll
    for (int ks = 0; ks < 8; ks++) {
      const int kc2 = (ks & 3) * 2;
      uint32_t ap = abase + (ks >> 2) * 16384;
      uint32_t bp = bbase + (ks >> 2) * 8192;
      uint32_t a[2][4], b[2][4];
#pragma unroll
      for (int mt = 0; mt < 2; mt++) {
        uint32_t addr = ap + aRow[mt] * 128 + (((kc2 + aChO) ^ (aRow[mt] & 7)) << 4);
        ldmatrix_x4(a[mt][0], a[mt][1], a[mt][2], a[mt][3], addr);
      }
#pragma unroll
      for (int p = 0; p < 2; p++) {
        uint32_t addr = bp + bRow[p] * 128 + (((kc2 + bChO) ^ (bRow[p] & 7)) << 4);
        ldmatrix_x4(b[p][0], b[p][1], b[p][2], b[p][3], addr);
      }
#pragma unroll
      for (int mt = 0; mt < 2; mt++)
#pragma unroll
        for (int nt = 0; nt < 4; nt++) {
          uint32_t b0 = b[nt >> 1][(nt & 1) ? 2 : 0];
          uint32_t b1 = b[nt >> 1][(nt & 1) ? 3 : 1];
          mma16816(acc[mt][nt], a[mt][0], a[mt][1], a[mt][2], a[mt][3], b0, b1);
        }
    }
  };

#pragma unroll
  for (int s = 0; s < STAGES - 1; s++) {
    load_stage(s, s);
    asm volatile("cp.async.commit_group;" ::: "memory");
  }
  for (int it = 0; it < NIT; ++it) {
    int s = it & (STAGES - 1);
    asm volatile("cp.async.wait_group %0;" :: "n"(STAGES - 2) : "memory");
    __syncthreads();
    int pf = it + STAGES - 1;
    if (pf < NIT) load_stage(pf & (STAGES - 1), pf);
    asm volatile("cp.async.commit_group;" ::: "memory");
    compute_stage(s);
  }

  const int g = lane >> 2, tg = lane & 3;
#pragma unroll
  for (int mt = 0; mt < 2; mt++)
#pragma unroll
    for (int nt = 0; nt < 4; nt++) {
      int row0 = wm + mt * 16 + g;
      int col0 = n0 + wn + nt * 8 + tg * 2;
      *(__half2*)(C + (size_t)row0 * ldC + col0) =
          __floats2half2_rn(acc[mt][nt][0], acc[mt][nt][1]);
      *(__half2*)(C + (size_t)(row0 + 8) * ldC + col0) =
          __floats2half2_rn(acc[mt][nt][2], acc[mt][nt][3]);
    }
}

// ===== GEMM 2 (LN fused): C fp16 = LN_cols(A[128,K] @ B[K,Ntot]), B N-major ===
__global__ __launch_bounds__(256, 1)
void gemm_tn_ln(const __half* __restrict__ A, const __half* __restrict__ B, int ldB,
                __half* __restrict__ C, int ldC,
                const float* __restrict__ gam, const float* __restrict__ bet) {
  extern __shared__ char smem[];
  uint32_t sb = smem_u32(smem);
  const int tid = threadIdx.x;
  const int wid = tid >> 5, lane = tid & 31;
  const int n0 = blockIdx.x * NTILE;
  const int wm = (wid & 3) * 32;
  const int wn = (wid >> 2) * 32;

  const int lj = lane >> 3, lr = lane & 7;
  int aRow[2];
  aRow[0] = wm + ((lj & 1) << 3) + lr;
  aRow[1] = aRow[0] + 16;
  const int aChO = lj >> 1;
  const int bKsub = ((lj & 1) << 3) + lr;
  const int bChSub = (wn >> 3) + (lj >> 1);

  float acc[2][4][4];
#pragma unroll
  for (int i = 0; i < 2; i++)
#pragma unroll
    for (int j = 0; j < 4; j++)
#pragma unroll
      for (int q = 0; q < 4; q++) acc[i][j][q] = 0.f;

  auto load_stage = [&](int s, int kc) {
    uint32_t base = sb + s * STAGE_BYTES;
    const __half* Ak = A + (size_t)kc * KTILE;
    const __half* Bk = B + (size_t)kc * KTILE * ldB + n0;
#pragma unroll
    for (int j = 0; j < 8; j++) {
      int idx = tid + j * 256;
      int c = idx & 15, row = idx >> 4;
      int panel = c >> 3, pc = c & 7;
      cp_async16(base + panel * 16384 + swz(row * 128 + pc * 16),
                 Ak + (size_t)row * KK + c * 8);
    }
#pragma unroll
    for (int j = 0; j < 4; j++) {
      int idx = tid + j * 256;
      int c = idx & 7, row = idx >> 3;
      cp_async16(base + A_STAGE_BYTES + swz(row * 128 + c * 16),
                 Bk + (size_t)row * ldB + c * 8);
    }
  };

  auto compute_stage = [&](int s) {
    uint32_t abase = sb + s * STAGE_BYTES;
    uint32_t bbase = abase + A_STAGE_BYTES;
#pragma unroll
    for (int ks = 0; ks < 8; ks++) {
      const int kc2 = (ks & 3) * 2;
      uint32_t ap = abase + (ks >> 2) * 16384;
      uint32_t a[2][4], b[2][4];
#pragma unroll
      for (int mt = 0; mt < 2; mt++) {
        uint32_t addr = ap + aRow[mt] * 128 + (((kc2 + aChO) ^ (aRow[mt] & 7)) << 4);
        ldmatrix_x4(a[mt][0], a[mt][1], a[mt][2], a[mt][3], addr);
      }
      int krow = ks * 16 + bKsub;
#pragma unroll
      for (int p = 0; p < 2; p++) {
        int chunk = bChSub + p * 2;
        uint32_t addr = bbase + krow * 128 + ((chunk ^ (krow & 7)) << 4);
        ldmatrix_x4t(b[p][0], b[p][1], b[p][2], b[p][3], addr);
      }
#pragma unroll
      for (int mt = 0; mt < 2; mt++)
#pragma unroll
        for (int nt = 0; nt < 4; nt++) {
          uint32_t b0 = b[nt >> 1][(nt & 1) << 1];
          uint32_t b1 = b[nt >> 1][((nt & 1) << 1) + 1];
          mma16816(acc[mt][nt], a[mt][0], a[mt][1], a[mt][2], a[mt][3], b0, b1);
        }
    }
  };

#pragma unroll
  for (int s = 0; s < STAGES - 1; s++) {
    load_stage(s, s);
    asm volatile("cp.async.commit_group;" ::: "memory");
  }
  for (int it = 0; it < NIT; ++it) {
    int s = it & (STAGES - 1);
    asm volatile("cp.async.wait_group %0;" :: "n"(STAGES - 2) : "memory");
    __syncthreads();
    int pf = it + STAGES - 1;
    if (pf < NIT) load_stage(pf & (STAGES - 1), pf);
    asm volatile("cp.async.commit_group;" ::: "memory");
    compute_stage(s);
  }

  const int g = lane >> 2, tg = lane & 3;

  asm volatile("cp.async.wait_group 0;" ::: "memory");
  __syncthreads();
  float* s_sum = reinterpret_cast<float*>(smem);          // [4][64]
  float* s_sq  = reinterpret_cast<float*>(smem) + 256;    // [4][64]

  float ps[4][2], pq[4][2];
#pragma unroll
  for (int nt = 0; nt < 4; nt++)
#pragma unroll
    for (int j = 0; j < 2; j++) {
      float sv = 0.f, qv = 0.f;
#pragma unroll
      for (int mt = 0; mt < 2; mt++) {
        float v0 = acc[mt][nt][j], v1 = acc[mt][nt][j + 2];
        sv += v0 + v1;
        qv += v0 * v0 + v1 * v1;
      }
#pragma unroll
      for (int o = 4; o < 32; o <<= 1) {
        sv += __shfl_xor_sync(0xffffffffu, sv, o);
        qv += __shfl_xor_sync(0xffffffffu, qv, o);
      }
      ps[nt][j] = sv;
      pq[nt][j] = qv;
    }
  if (g == 0) {
    int mw = wid & 3;
#pragma unroll
    for (int nt = 0; nt < 4; nt++)
#pragma unroll
      for (int j = 0; j < 2; j++) {
        int col = wn + nt * 8 + tg * 2 + j;
        s_sum[mw * 64 + col] = ps[nt][j];
        s_sq[mw * 64 + col] = pq[nt][j];
      }
  }
  __syncthreads();

  float mean[4][2], rinv[4][2];
#pragma unroll
  for (int nt = 0; nt < 4; nt++)
#pragma unroll
    for (int j = 0; j < 2; j++) {
      int col = wn + nt * 8 + tg * 2 + j;
      float tot = s_sum[col] + s_sum[64 + col] + s_sum[128 + col] + s_sum[192 + col];
      float tq  = s_sq[col] + s_sq[64 + col] + s_sq[128 + col] + s_sq[192 + col];
      float m = tot * (1.0f / DD);
      float var = tq * (1.0f / DD) - m * m;
      mean[nt][j] = m;
      rinv[nt][j] = rsqrtf(var + LN_EPS);
    }

#pragma unroll
  for (int mt = 0; mt < 2; mt++) {
    int r0 = wm + mt * 16 + g;
    float g0 = gam[r0], b0 = bet[r0];
    float g1 = gam[r0 + 8], b1 = bet[r0 + 8];
#pragma unroll
    for (int nt = 0; nt < 4; nt++) {
      int col0 = n0 + wn + nt * 8 + tg * 2;
      float y00 = (acc[mt][nt][0] - mean[nt][0]) * rinv[nt][0] * g0 + b0;
      float y01 = (acc[mt][nt][1] - mean[nt][1]) * rinv[nt][1] * g0 + b0;
      float y10 = (acc[mt][nt][2] - mean[nt][0]) * rinv[nt][0] * g1 + b1;
      float y11 = (acc[mt][nt][3] - mean[nt][1]) * rinv[nt][1] * g1 + b1;
      *(__half2*)(C + (size_t)r0 * ldC + col0) = __floats2half2_rn(y00, y01);
      *(__half2*)(C + (size_t)(r0 + 8) * ldC + col0) = __floats2half2_rn(y10, y11);
    }
  }
}

// ===== Final GEMM with fused h conversion + counts (KTILE=64) ================
__global__ __launch_bounds__(256, 1)
void gemm_tn_hcv(const __half* __restrict__ A, const int* __restrict__ H,
                 int kIters, float* __restrict__ Cp, int ldC,
                 float* __restrict__ counts) {
  extern __shared__ char smem[];
  uint32_t sb = smem_u32(smem);
  const int tid = threadIdx.x;
  const int wid = tid >> 5, lane = tid & 31;
  const int n0 = blockIdx.x * NTILE;
  const int kOff = blockIdx.y * kIters;
  const int wm = (wid & 3) * 32;
  const int wn = (wid >> 2) * 32;

  const int lj = lane >> 3, lr = lane & 7;
  int aRow[2];
  aRow[0] = wm + ((lj & 1) << 3) + lr;
  aRow[1] = aRow[0] + 16;
  const int aChO = lj >> 1;
  const int bKsub = ((lj & 1) << 3) + lr;
  const int bChSub = (wn >> 3) + (lj >> 1);

  float acc[2][4][4];
#pragma unroll
  for (int i = 0; i < 2; i++)
#pragma unroll
    for (int j = 0; j < 4; j++)
#pragma unroll
      for (int q = 0; q < 4; q++) acc[i][j][q] = 0.f;

  float cnt[16];
#pragma unroll
  for (int j = 0; j < 16; j++) cnt[j] = 0.f;

  auto load_stage = [&](int s, int kc) {
    const __half* Ak = A + (size_t)kc * HKT;
    const int* Hk = H + (size_t)kc * HKT * EE + n0;
#pragma unroll
    for (int j = 0; j < 4; j++) {
      int idx = tid + j * 256;
      int c = idx & 7, row = idx >> 3;
      cp_async16(sb + CV_A_OFF + s * 16384 + swz(row * 128 + c * 16),
                 Ak + (size_t)row * KK + c * 8);
    }
#pragma unroll
    for (int j = 0; j < 4; j++) {
      int idx = tid + j * 256;
      int c = idx & 15, row = idx >> 4;   // 64 k-rows x 16 chunks of 16B
      cp_async16(sb + CV_B32_OFF + s * 16384 + row * 256 + c * 16,
                 Hk + (size_t)row * EE + c * 4);
    }
  };

#pragma unroll
  for (int s = 0; s < STAGES - 1; s++) {
    load_stage(s, kOff + s);
    asm volatile("cp.async.commit_group;" ::: "memory");
  }
  const int cR = tid >> 2, cQ = tid & 3;
  for (int it = 0; it < kIters; ++it) {
    int s = it & (STAGES - 1);
    asm volatile("cp.async.wait_group %0;" :: "n"(STAGES - 2) : "memory");
    __syncthreads();
    {
      const int4* p = (const int4*)(smem + CV_B32_OFF + s * 16384 + cR * 256 + cQ * 64);
      int4 v0 = p[0], v1 = p[1], v2 = p[2], v3 = p[3];
      float f[16];
      f[0] = (v0.x > 0) ? 1.f : 0.f;  f[1] = (v0.y > 0) ? 1.f : 0.f;
      f[2] = (v0.z > 0) ? 1.f : 0.f;  f[3] = (v0.w > 0) ? 1.f : 0.f;
      f[4] = (v1.x > 0) ? 1.f : 0.f;  f[5] = (v1.y > 0) ? 1.f : 0.f;
      f[6] = (v1.z > 0) ? 1.f : 0.f;  f[7] = (v1.w > 0) ? 1.f : 0.f;
      f[8] = (v2.x > 0) ? 1.f : 0.f;  f[9] = (v2.y > 0) ? 1.f : 0.f;
      f[10] = (v2.z > 0) ? 1.f : 0.f; f[11] = (v2.w > 0) ? 1.f : 0.f;
      f[12] = (v3.x > 0) ? 1.f : 0.f; f[13] = (v3.y > 0) ? 1.f : 0.f;
      f[14] = (v3.z > 0) ? 1.f : 0.f; f[15] = (v3.w > 0) ? 1.f : 0.f;
#pragma unroll
      for (int j = 0; j < 16; j++) cnt[j] += f[j];
      uint4 u0, u1;
      u0.x = h2u(__floats2half2_rn(f[0], f[1]));
      u0.y = h2u(__floats2half2_rn(f[2], f[3]));
      u0.z = h2u(__floats2half2_rn(f[4], f[5]));
      u0.w = h2u(__floats2half2_rn(f[6], f[7]));
      u1.x = h2u(__floats2half2_rn(f[8], f[9]));
      u1.y = h2u(__floats2half2_rn(f[10], f[11]));
      u1.z = h2u(__floats2half2_rn(f[12], f[13]));
      u1.w = h2u(__floats2half2_rn(f[14], f[15]));
      *(uint4*)(smem + CV_B16_OFF + swz(cR * 128 + cQ * 32)) = u0;
      *(uint4*)(smem + CV_B16_OFF + swz(cR * 128 + cQ * 32 + 16)) = u1;
    }
    int pf = it + STAGES - 1;
    if (pf < kIters) load_stage(pf & (STAGES - 1), kOff + pf);
    asm volatile("cp.async.commit_group;" ::: "memory");
    __syncthreads();  // B16 visible
    {
      uint32_t abase = sb + CV_A_OFF + s * 16384;
      uint32_t bbase = sb + CV_B16_OFF;
#pragma unroll
      for (int ks = 0; ks < 4; ks++) {
        const int kc2 = ks * 2;
        uint32_t a[2][4], b[2][4];
#pragma unroll
        for (int mt = 0; mt < 2; mt++) {
          uint32_t addr = abase + aRow[mt] * 128 + (((kc2 + aChO) ^ (aRow[mt] & 7)) << 4);
          ldmatrix_x4(a[mt][0], a[mt][1], a[mt][2], a[mt][3], addr);
        }
        int krow = ks * 16 + bKsub;
#pragma unroll
        for (int p = 0; p < 2; p++) {
          int chunk = bChSub + p * 2;
          uint32_t addr = bbase + krow * 128 + ((chunk ^ (krow & 7)) << 4);
          ldmatrix_x4t(b[p][0], b[p][1], b[p][2], b[p][3], addr);
        }
#pragma unroll
        for (int mt = 0; mt < 2; mt++)
#pragma unroll
          for (int nt = 0; nt < 4; nt++) {
            uint32_t b0 = b[nt >> 1][(nt & 1) << 1];
            uint32_t b1 = b[nt >> 1][((nt & 1) << 1) + 1];
            mma16816(acc[mt][nt], a[mt][0], a[mt][1], a[mt][2], a[mt][3], b0, b1);
          }
      }
    }
  }

  float* C = Cp + (size_t)blockIdx.y * DD * EE;
  const int g = lane >> 2, tg = lane & 3;
#pragma unroll
  for (int mt = 0; mt < 2; mt++)
#pragma unroll
    for (int nt = 0; nt < 4; nt++) {
      int row0 = wm + mt * 16 + g;
      int col0 = n0 + wn + nt * 8 + tg * 2;
      *(float2*)(C + (size_t)row0 * ldC + col0) =
          make_float2(acc[mt][nt][0], acc[mt][nt][1]);
      *(float2*)(C + (size_t)(row0 + 8) * ldC + col0) =
          make_float2(acc[mt][nt][2], acc[mt][nt][3]);
    }

#pragma unroll
  for (int j = 0; j < 16; j++) {
#pragma unroll
    for (int o = 4; o < 32; o <<= 1)
      cnt[j] += __shfl_xor_sync(0xffffffffu, cnt[j], o);
  }
  if (lane < 4) {
#pragma unroll
    for (int j = 0; j < 16; j++)
      atomicAdd(&counts[n0 + cQ * 16 + j], cnt[j]);
  }
}

// ---------------- conversion / aux kernels ----------------
__global__ void k_convT(const float* __restrict__ T, __half* __restrict__ Th) {
  size_t i = (size_t)blockIdx.x * blockDim.x + threadIdx.x;
  size_t n8 = (size_t)NN * NN / 8;
  const float4* src = (const float4*)T;
  uint4* dst = (uint4*)Th;
  for (size_t j = i; j < n8; j += (size_t)gridDim.x * blockDim.x) {
    float4 a = src[2 * j], b = src[2 * j + 1];
    uint4 o;
    o.x = h2u(__floats2half2_rn(a.x, a.y));
    o.y = h2u(__floats2half2_rn(a.z, a.w));
    o.z = h2u(__floats2half2_rn(b.x, b.y));
    o.w = h2u(__floats2half2_rn(b.z, b.w));
    dst[j] = o;
  }
}

__global__ void k_conv_x0(const float* __restrict__ x0, __half* __restrict__ Xh) {
  __shared__ float t[32][33];
  int d0 = blockIdx.x << 5, n0 = blockIdx.y << 5;
  int x = threadIdx.x, y = threadIdx.y;
#pragma unroll
  for (int i = 0; i < 32; i += 8)
    t[y + i][x] = x0[(size_t)(n0 + y + i) * DD + d0 + x];
  __syncthreads();
#pragma unroll
  for (int i = 0; i < 32; i += 8)
    Xh[(size_t)(d0 + y + i) * NN + n0 + x] = __float2half(t[x][y + i]);
}

__global__ void k_zero(float* __restrict__ p, int n) {
  int i = blockIdx.x * blockDim.x + threadIdx.x;
  if (i < n) p[i] = 0.0f;
}

__global__ void k_final_max(const float* __restrict__ S, const float* __restrict__ counts,
                            float* __restrict__ out) {
  int d = blockIdx.x;
  const float* S0 = S + (size_t)d * EE;
  const float* S1 = S + (size_t)DD * EE + (size_t)d * EE;
  float m = -3.402823466e38f;
  for (int e = threadIdx.x; e < EE; e += blockDim.x)
    m = fmaxf(m, (S0[e] + S1[e]) / counts[e]);
#pragma unroll
  for (int o = 16; o > 0; o >>= 1) m = fmaxf(m, __shfl_xor_sync(0xffffffffu, m, o));
  __shared__ float red[4];
  int lane = threadIdx.x & 31, w = threadIdx.x >> 5;
  if (lane == 0) red[w] = m;
  __syncthreads();
  if (threadIdx.x == 0)
    out[d] = fmaxf(fmaxf(red[0], red[1]), fmaxf(red[2], red[3]));
}

// ---------------- launch ----------------
extern "C" void kernel_launch(void* const* d_in, const int* in_sizes, int n_in,
                              void* d_out, int out_size) {
  const float* x0  = (const float*)d_in[0];  // [8192,128]
  const float* T   = (const float*)d_in[1];  // [8192,8192]
  const float* gam = (const float*)d_in[2];  // [128]
  const float* bet = (const float*)d_in[3];  // [128]
  const int*   h   = (const int*)d_in[4];    // [8192,4096]
  float* out = (float*)d_out;                // [128]

  __half *Th, *Xh, *Tbh;
  float *S, *counts;
  cudaGetSymbolAddress((void**)&Th,  g_Th);
  cudaGetSymbolAddress((void**)&Xh,  g_Xh);
  cudaGetSymbolAddress((void**)&Tbh, g_Tbh);
  cudaGetSymbolAddress((void**)&S,   g_S);
  cudaGetSymbolAddress((void**)&counts, g_counts);

  cudaFuncSetAttribute(gemm_nt, cudaFuncAttributeMaxDynamicSharedMemorySize, GEMM_SMEM);
  cudaFuncSetAttribute(gemm_tn_ln, cudaFuncAttributeMaxDynamicSharedMemorySize, GEMM_SMEM);
  cudaFuncSetAttribute(gemm_tn_hcv, cudaFuncAttributeMaxDynamicSharedMemorySize, HCV_SMEM);

  k_conv_x0<<<dim3(DD / 32, NN / 32), dim3(32, 8)>>>(x0, Xh);   // launch 1
  k_zero<<<(EE + 255) / 256, 256>>>(counts, EE);                // launch 2
  k_convT<<<4096, 256>>>(T, Th);                                // launch 3

  for (int l = 0; l < 3; ++l) {  // num_layers fixed at 3 by setup_inputs
    gemm_nt<<<NN / NTILE, 256, GEMM_SMEM>>>(Xh, Th, Tbh, NN);   // launch 4 = profiled
    gemm_tn_ln<<<NN / NTILE, 256, GEMM_SMEM>>>(Tbh, Th, NN, Xh, NN, gam, bet);
  }
  // final: sums^T = x^T @ float(h>0), h converted in-kernel, split-K=2
  gemm_tn_hcv<<<dim3(EE / NTILE, 2), 256, HCV_SMEM>>>(Xh, h, (KK / HKT) / 2, S, EE, counts);
  k_final_max<<<DD, 128>>>(S, counts, out);
}

// round 16
// speedup vs baseline: 1.0419x; 1.0030x over previous
#include <cuda_runtime.h>
#include <cuda_fp16.h>
#include <cstdint>

// Problem sizes (fixed by setup_inputs)
#define NN 8192   // nodes
#define DD 128    // embedding dim
#define EE 4096   // hyperedges
#define KK 8192   // reduction dim of the big GEMMs
#define LN_EPS 1e-5f

// ---------------- GEMM config: 128x64 tile, KTILE=128 (2 swizzle panels) -----
#define KTILE 128                      // halfs per k-chunk = 2 x 128B panels
#define NTILE 64
#define STAGES 4
#define NIT (KK / KTILE)               // 64 k-iterations
#define A_STAGE_BYTES (2 * 16384)      // 32 KB: 2 panels (128 rows x 128B)
#define B_STAGE_BYTES (2 * 8192)       // 16 KB: 2 panels (64 rows x 128B)
#define STAGE_BYTES (A_STAGE_BYTES + B_STAGE_BYTES)   // 48 KB
#define GEMM_SMEM (STAGES * STAGE_BYTES)              // 192 KB

// hcv kernel (KTILE=64): A pool 64KB | B32 pool 64KB | B16 8KB
#define HKT 64
#define CV_A_OFF 0
#define CV_B32_OFF (4 * 16384)
#define CV_B16_OFF (8 * 16384)
#define HCV_SMEM (CV_B16_OFF + 8192)   // 139264 B

// prep kernel block partition
#define PREP_CONVT_BLKS 1184           // 8 x 148
#define PREP_X0_BLKS 1024              // (DD/32) x (NN/32)
#define PREP_ZERO_BLKS 4               // EE / 1024
#define PREP_GRID (PREP_CONVT_BLKS + PREP_X0_BLKS + PREP_ZERO_BLKS)

// ---------------- scratch (device globals; no allocation allowed) ------------
__device__ __half g_Th [(size_t)NN * NN];     // T fp16             128 MB
__device__ __half g_Xh [(size_t)DD * NN];     // x^T fp16             2 MB
__device__ __half g_Tbh[(size_t)DD * NN];     // t^T fp16             2 MB
__device__ float  g_S  [(size_t)2 * DD * EE]; // final partials       4 MB
__device__ float  g_counts[EE];

// ---------------- helpers ----------------
__device__ __forceinline__ uint32_t h2u(__half2 h) {
  uint32_t u;
  *reinterpret_cast<__half2*>(&u) = h;
  return u;
}
__device__ __forceinline__ uint32_t smem_u32(const void* p) {
  uint32_t a;
  asm("{ .reg .u64 t; cvta.to.shared.u64 t, %1; cvt.u32.u64 %0, t; }" : "=r"(a) : "l"(p));
  return a;
}
__device__ __forceinline__ uint32_t swz(uint32_t b) { return b ^ ((b >> 3) & 0x70); }
__device__ __forceinline__ void cp_async16(uint32_t dst, const void* src) {
  asm volatile("cp.async.cg.shared.global [%0], [%1], 16;" :: "r"(dst), "l"(src));
}
__device__ __forceinline__ void ldmatrix_x4(uint32_t& r0, uint32_t& r1, uint32_t& r2,
                                            uint32_t& r3, uint32_t addr) {
  asm volatile("ldmatrix.sync.aligned.m8n8.x4.shared.b16 {%0,%1,%2,%3}, [%4];"
               : "=r"(r0), "=r"(r1), "=r"(r2), "=r"(r3) : "r"(addr));
}
__device__ __forceinline__ void ldmatrix_x4t(uint32_t& r0, uint32_t& r1, uint32_t& r2,
                                             uint32_t& r3, uint32_t addr) {
  asm volatile("ldmatrix.sync.aligned.m8n8.x4.trans.shared.b16 {%0,%1,%2,%3}, [%4];"
               : "=r"(r0), "=r"(r1), "=r"(r2), "=r"(r3) : "r"(addr));
}
__device__ __forceinline__ void mma16816(float* c, uint32_t a0, uint32_t a1, uint32_t a2,
                                         uint32_t a3, uint32_t b0, uint32_t b1) {
  asm volatile(
      "mma.sync.aligned.m16n8k16.row.col.f32.f16.f16.f32 "
      "{%0,%1,%2,%3}, {%4,%5,%6,%7}, {%8,%9}, {%0,%1,%2,%3};"
      : "+f"(c[0]), "+f"(c[1]), "+f"(c[2]), "+f"(c[3])
      : "r"(a0), "r"(a1), "r"(a2), "r"(a3), "r"(b0), "r"(b1));
}

// ============ GEMM 1: C[128,Ntot] = A[128,K] @ B[Ntot,K]^T, B K-major =========
__global__ __launch_bounds__(256, 1)
void gemm_nt(const __half* __restrict__ A, const __half* __restrict__ B,
             __half* __restrict__ C, int ldC) {
  extern __shared__ char smem[];
  uint32_t sb = smem_u32(smem);
  const int tid = threadIdx.x;
  const int wid = tid >> 5, lane = tid & 31;
  const int n0 = blockIdx.x * NTILE;
  const int wm = (wid & 3) * 32;
  const int wn = (wid >> 2) * 32;

  const int lj = lane >> 3, lr = lane & 7;
  int aRow[2], bRow[2];
  aRow[0] = wm + ((lj & 1) << 3) + lr;
  aRow[1] = aRow[0] + 16;
  const int aChO = lj >> 1;
  bRow[0] = wn + ((lj >> 1) << 3) + lr;
  bRow[1] = bRow[0] + 16;
  const int bChO = lj & 1;

  float acc[2][4][4];
#pragma unroll
  for (int i = 0; i < 2; i++)
#pragma unroll
    for (int j = 0; j < 4; j++)
#pragma unroll
      for (int q = 0; q < 4; q++) acc[i][j][q] = 0.f;

  auto load_stage = [&](int s, int kc) {
    uint32_t base = sb + s * STAGE_BYTES;
    const __half* Ak = A + (size_t)kc * KTILE;
    const __half* Bk = B + (size_t)n0 * KK + (size_t)kc * KTILE;
#pragma unroll
    for (int j = 0; j < 8; j++) {
      int idx = tid + j * 256;
      int c = idx & 15, row = idx >> 4;
      int panel = c >> 3, pc = c & 7;
      cp_async16(base + panel * 16384 + swz(row * 128 + pc * 16),
                 Ak + (size_t)row * KK + c * 8);
    }
#pragma unroll
    for (int j = 0; j < 4; j++) {
      int idx = tid + j * 256;
      int c = idx & 15, row = idx >> 4;
      int panel = c >> 3, pc = c & 7;
      cp_async16(base + A_STAGE_BYTES + panel * 8192 + swz(row * 128 + pc * 16),
                 Bk + (size_t)row * KK + c * 8);
    }
  };

  auto compute_stage = [&](int s) {
    uint32_t abase = sb + s * STAGE_BYTES;
    uint32_t bbase = abase + A_STAGE_BYTES;
#pragma unroll
    for (int ks = 0; ks < 8; ks++) {
      const int kc2 = (ks & 3) * 2;
      uint32_t ap = abase + (ks >> 2) * 16384;
      uint32_t bp = bbase + (ks >> 2) * 8192;
      uint32_t a[2][4], b[2][4];
#pragma unroll
      for (int mt = 0; mt < 2; mt++) {
        uint32_t addr = ap + aRow[mt] * 128 + (((kc2 + aChO) ^ (aRow[mt] & 7)) << 4);
        ldmatrix_x4(a[mt][0], a[mt][1], a[mt][2], a[mt][3], addr);
      }
#pragma unroll
      for (int p = 0; p < 2; p++) {
        uint32_t addr = bp + bRow[p] * 128 + (((kc2 + bChO) ^ (bRow[p] & 7)) << 4);
        ldmatrix_x4(b[p][0], b[p][1], b[p][2], b[p][3], addr);
      }
#pragma unroll
      for (int mt = 0; mt < 2; mt++)
#pragma unroll
        for (int nt = 0; nt < 4; nt++) {
          uint32_t b0 = b[nt >> 1][(nt & 1) ? 2 : 0];
          uint32_t b1 = b[nt >> 1][(nt & 1) ? 3 : 1];
          mma16816(acc[mt][nt], a[mt][0], a[mt][1], a[mt][2], a[mt][3], b0, b1);
        }
    }
  };

#pragma unroll
  for (int s = 0; s < STAGES - 1; s++) {
    load_stage(s, s);
    asm volatile("cp.async.commit_group;" ::: "memory");
  }
  for (int it = 0; it < NIT; ++it) {
    int s = it & (STAGES - 1);
    asm volatile("cp.async.wait_group %0;" :: "n"(STAGES - 2) : "memory");
    __syncthreads();
    int pf = it + STAGES - 1;
    if (pf < NIT) load_stage(pf & (STAGES - 1), pf);
    asm volatile("cp.async.commit_group;" ::: "memory");
    compute_stage(s);
  }

  const int g = lane >> 2, tg = lane & 3;
#pragma unroll
  for (int mt = 0; mt < 2; mt++)
#pragma unroll
    for (int nt = 0; nt < 4; nt++) {
      int row0 = wm + mt * 16 + g;
      int col0 = n0 + wn + nt * 8 + tg * 2;
      *(__half2*)(C + (size_t)row0 * ldC + col0) =
          __floats2half2_rn(acc[mt][nt][0], acc[mt][nt][1]);
      *(__half2*)(C + (size_t)(row0 + 8) * ldC + col0) =
          __floats2half2_rn(acc[mt][nt][2], acc[mt][nt][3]);
    }
}

// ===== GEMM 2 (LN fused): C fp16 = LN_cols(A[128,K] @ B[K,Ntot]), B N-major ===
__global__ __launch_bounds__(256, 1)
void gemm_tn_ln(const __half* __restrict__ A, const __half* __restrict__ B, int ldB,
                __half* __restrict__ C, int ldC,
                const float* __restrict__ gam, const float* __restrict__ bet) {
  extern __shared__ char smem[];
  uint32_t sb = smem_u32(smem);
  const int tid = threadIdx.x;
  const int wid = tid >> 5, lane = tid & 31;
  const int n0 = blockIdx.x * NTILE;
  const int wm = (wid & 3) * 32;
  const int wn = (wid >> 2) * 32;

  const int lj = lane >> 3, lr = lane & 7;
  int aRow[2];
  aRow[0] = wm + ((lj & 1) << 3) + lr;
  aRow[1] = aRow[0] + 16;
  const int aChO = lj >> 1;
  const int bKsub = ((lj & 1) << 3) + lr;
  const int bChSub = (wn >> 3) + (lj >> 1);

  float acc[2][4][4];
#pragma unroll
  for (int i = 0; i < 2; i++)
#pragma unroll
    for (int j = 0; j < 4; j++)
#pragma unroll
      for (int q = 0; q < 4; q++) acc[i][j][q] = 0.f;

  auto load_stage = [&](int s, int kc) {
    uint32_t base = sb + s * STAGE_BYTES;
    const __half* Ak = A + (size_t)kc * KTILE;
    const __half* Bk = B + (size_t)kc * KTILE * ldB + n0;
#pragma unroll
    for (int j = 0; j < 8; j++) {
      int idx = tid + j * 256;
      int c = idx & 15, row = idx >> 4;
      int panel = c >> 3, pc = c & 7;
      cp_async16(base + panel * 16384 + swz(row * 128 + pc * 16),
                 Ak + (size_t)row * KK + c * 8);
    }
#pragma unroll
    for (int j = 0; j < 4; j++) {
      int idx = tid + j * 256;
      int c = idx & 7, row = idx >> 3;
      cp_async16(base + A_STAGE_BYTES + swz(row * 128 + c * 16),
                 Bk + (size_t)row * ldB + c * 8);
    }
  };

  auto compute_stage = [&](int s) {
    uint32_t abase = sb + s * STAGE_BYTES;
    uint32_t bbase = abase + A_STAGE_BYTES;
#pragma unroll
    for (int ks = 0; ks < 8; ks++) {
      const int kc2 = (ks & 3) * 2;
      uint32_t ap = abase + (ks >> 2) * 16384;
      uint32_t a[2][4], b[2][4];
#pragma unroll
      for (int mt = 0; mt < 2; mt++) {
        uint32_t addr = ap + aRow[mt] * 128 + (((kc2 + aChO) ^ (aRow[mt] & 7)) << 4);
        ldmatrix_x4(a[mt][0], a[mt][1], a[mt][2], a[mt][3], addr);
      }
      int krow = ks * 16 + bKsub;
#pragma unroll
      for (int p = 0; p < 2; p++) {
        int chunk = bChSub + p * 2;
        uint32_t addr = bbase + krow * 128 + ((chunk ^ (krow & 7)) << 4);
        ldmatrix_x4t(b[p][0], b[p][1], b[p][2], b[p][3], addr);
      }
#pragma unroll
      for (int mt = 0; mt < 2; mt++)
#pragma unroll
        for (int nt = 0; nt < 4; nt++) {
          uint32_t b0 = b[nt >> 1][(nt & 1) << 1];
          uint32_t b1 = b[nt >> 1][((nt & 1) << 1) + 1];
          mma16816(acc[mt][nt], a[mt][0], a[mt][1], a[mt][2], a[mt][3], b0, b1);
        }
    }
  };

#pragma unroll
  for (int s = 0; s < STAGES - 1; s++) {
    load_stage(s, s);
    asm volatile("cp.async.commit_group;" ::: "memory");
  }
  for (int it = 0; it < NIT; ++it) {
    int s = it & (STAGES - 1);
    asm volatile("cp.async.wait_group %0;" :: "n"(STAGES - 2) : "memory");
    __syncthreads();
    int pf = it + STAGES - 1;
    if (pf < NIT) load_stage(pf & (STAGES - 1), pf);
    asm volatile("cp.async.commit_group;" ::: "memory");
    compute_stage(s);
  }

  const int g = lane >> 2, tg = lane & 3;

  asm volatile("cp.async.wait_group 0;" ::: "memory");
  __syncthreads();
  float* s_sum = reinterpret_cast<float*>(smem);          // [4][64]
  float* s_sq  = reinterpret_cast<float*>(smem) + 256;    // [4][64]

  float ps[4][2], pq[4][2];
#pragma unroll
  for (int nt = 0; nt < 4; nt++)
#pragma unroll
    for (int j = 0; j < 2; j++) {
      float sv = 0.f, qv = 0.f;
#pragma unroll
      for (int mt = 0; mt < 2; mt++) {
        float v0 = acc[mt][nt][j], v1 = acc[mt][nt][j + 2];
        sv += v0 + v1;
        qv += v0 * v0 + v1 * v1;
      }
#pragma unroll
      for (int o = 4; o < 32; o <<= 1) {
        sv += __shfl_xor_sync(0xffffffffu, sv, o);
        qv += __shfl_xor_sync(0xffffffffu, qv, o);
      }
      ps[nt][j] = sv;
      pq[nt][j] = qv;
    }
  if (g == 0) {
    int mw = wid & 3;
#pragma unroll
    for (int nt = 0; nt < 4; nt++)
#pragma unroll
      for (int j = 0; j < 2; j++) {
        int col = wn + nt * 8 + tg * 2 + j;
        s_sum[mw * 64 + col] = ps[nt][j];
        s_sq[mw * 64 + col] = pq[nt][j];
      }
  }
  __syncthreads();

  float mean[4][2], rinv[4][2];
#pragma unroll
  for (int nt = 0; nt < 4; nt++)
#pragma unroll
    for (int j = 0; j < 2; j++) {
      int col = wn + nt * 8 + tg * 2 + j;
      float tot = s_sum[col] + s_sum[64 + col] + s_sum[128 + col] + s_sum[192 + col];
      float tq  = s_sq[col] + s_sq[64 + col] + s_sq[128 + col] + s_sq[192 + col];
      float m = tot * (1.0f / DD);
      float var = tq * (1.0f / DD) - m * m;
      mean[nt][j] = m;
      rinv[nt][j] = rsqrtf(var + LN_EPS);
    }

#pragma unroll
  for (int mt = 0; mt < 2; mt++) {
    int r0 = wm + mt * 16 + g;
    float g0 = gam[r0], b0 = bet[r0];
    float g1 = gam[r0 + 8], b1 = bet[r0 + 8];
#pragma unroll
    for (int nt = 0; nt < 4; nt++) {
      int col0 = n0 + wn + nt * 8 + tg * 2;
      float y00 = (acc[mt][nt][0] - mean[nt][0]) * rinv[nt][0] * g0 + b0;
      float y01 = (acc[mt][nt][1] - mean[nt][1]) * rinv[nt][1] * g0 + b0;
      float y10 = (acc[mt][nt][2] - mean[nt][0]) * rinv[nt][0] * g1 + b1;
      float y11 = (acc[mt][nt][3] - mean[nt][1]) * rinv[nt][1] * g1 + b1;
      *(__half2*)(C + (size_t)r0 * ldC + col0) = __floats2half2_rn(y00, y01);
      *(__half2*)(C + (size_t)(r0 + 8) * ldC + col0) = __floats2half2_rn(y10, y11);
    }
  }
}

// ===== Final GEMM with fused h conversion + counts (KTILE=64) ================
__global__ __launch_bounds__(256, 1)
void gemm_tn_hcv(const __half* __restrict__ A, const int* __restrict__ H,
                 int kIters, float* __restrict__ Cp, int ldC,
                 float* __restrict__ counts) {
  extern __shared__ char smem[];
  uint32_t sb = smem_u32(smem);
  const int tid = threadIdx.x;
  const int wid = tid >> 5, lane = tid & 31;
  const int n0 = blockIdx.x * NTILE;
  const int kOff = blockIdx.y * kIters;
  const int wm = (wid & 3) * 32;
  const int wn = (wid >> 2) * 32;

  const int lj = lane >> 3, lr = lane & 7;
  int aRow[2];
  aRow[0] = wm + ((lj & 1) << 3) + lr;
  aRow[1] = aRow[0] + 16;
  const int aChO = lj >> 1;
  const int bKsub = ((lj & 1) << 3) + lr;
  const int bChSub = (wn >> 3) + (lj >> 1);

  float acc[2][4][4];
#pragma unroll
  for (int i = 0; i < 2; i++)
#pragma unroll
    for (int j = 0; j < 4; j++)
#pragma unroll
      for (int q = 0; q < 4; q++) acc[i][j][q] = 0.f;

  float cnt[16];
#pragma unroll
  for (int j = 0; j < 16; j++) cnt[j] = 0.f;

  auto load_stage = [&](int s, int kc) {
    const __half* Ak = A + (size_t)kc * HKT;
    const int* Hk = H + (size_t)kc * HKT * EE + n0;
#pragma unroll
    for (int j = 0; j < 4; j++) {
      int idx = tid + j * 256;
      int c = idx & 7, row = idx >> 3;
      cp_async16(sb + CV_A_OFF + s * 16384 + swz(row * 128 + c * 16),
                 Ak + (size_t)row * KK + c * 8);
    }
#pragma unroll
    for (int j = 0; j < 4; j++) {
      int idx = tid + j * 256;
      int c = idx & 15, row = idx >> 4;   // 64 k-rows x 16 chunks of 16B
      cp_async16(sb + CV_B32_OFF + s * 16384 + row * 256 + c * 16,
                 Hk + (size_t)row * EE + c * 4);
    }
  };

#pragma unroll
  for (int s = 0; s < STAGES - 1; s++) {
    load_stage(s, kOff + s);
    asm volatile("cp.async.commit_group;" ::: "memory");
  }
  const int cR = tid >> 2, cQ = tid & 3;
  for (int it = 0; it < kIters; ++it) {
    int s = it & (STAGES - 1);
    asm volatile("cp.async.wait_group %0;" :: "n"(STAGES - 2) : "memory");
    __syncthreads();
    {
      const int4* p = (const int4*)(smem + CV_B32_OFF + s * 16384 + cR * 256 + cQ * 64);
      int4 v0 = p[0], v1 = p[1], v2 = p[2], v3 = p[3];
      float f[16];
      f[0] = (v0.x > 0) ? 1.f : 0.f;  f[1] = (v0.y > 0) ? 1.f : 0.f;
      f[2] = (v0.z > 0) ? 1.f : 0.f;  f[3] = (v0.w > 0) ? 1.f : 0.f;
      f[4] = (v1.x > 0) ? 1.f : 0.f;  f[5] = (v1.y > 0) ? 1.f : 0.f;
      f[6] = (v1.z > 0) ? 1.f : 0.f;  f[7] = (v1.w > 0) ? 1.f : 0.f;
      f[8] = (v2.x > 0) ? 1.f : 0.f;  f[9] = (v2.y > 0) ? 1.f : 0.f;
      f[10] = (v2.z > 0) ? 1.f : 0.f; f[11] = (v2.w > 0) ? 1.f : 0.f;
      f[12] = (v3.x > 0) ? 1.f : 0.f; f[13] = (v3.y > 0) ? 1.f : 0.f;
      f[14] = (v3.z > 0) ? 1.f : 0.f; f[15] = (v3.w > 0) ? 1.f : 0.f;
#pragma unroll
      for (int j = 0; j < 16; j++) cnt[j] += f[j];
      uint4 u0, u1;
      u0.x = h2u(__floats2half2_rn(f[0], f[1]));
      u0.y = h2u(__floats2half2_rn(f[2], f[3]));
      u0.z = h2u(__floats2half2_rn(f[4], f[5]));
      u0.w = h2u(__floats2half2_rn(f[6], f[7]));
      u1.x = h2u(__floats2half2_rn(f[8], f[9]));
      u1.y = h2u(__floats2half2_rn(f[10], f[11]));
      u1.z = h2u(__floats2half2_rn(f[12], f[13]));
      u1.w = h2u(__floats2half2_rn(f[14], f[15]));
      *(uint4*)(smem + CV_B16_OFF + swz(cR * 128 + cQ * 32)) = u0;
      *(uint4*)(smem + CV_B16_OFF + swz(cR * 128 + cQ * 32 + 16)) = u1;
    }
    int pf = it + STAGES - 1;
    if (pf < kIters) load_stage(pf & (STAGES - 1), kOff + pf);
    asm volatile("cp.async.commit_group;" ::: "memory");
    __syncthreads();  // B16 visible
    {
      uint32_t abase = sb + CV_A_OFF + s * 16384;
      uint32_t bbase = sb + CV_B16_OFF;
#pragma unroll
      for (int ks = 0; ks < 4; ks++) {
        const int kc2 = ks * 2;
        uint32_t a[2][4], b[2][4];
#pragma unroll
        for (int mt = 0; mt < 2; mt++) {
          uint32_t addr = abase + aRow[mt] * 128 + (((kc2 + aChO) ^ (aRow[mt] & 7)) << 4);
          ldmatrix_x4(a[mt][0], a[mt][1], a[mt][2], a[mt][3], addr);
        }
        int krow = ks * 16 + bKsub;
#pragma unroll
        for (int p = 0; p < 2; p++) {
          int chunk = bChSub + p * 2;
          uint32_t addr = bbase + krow * 128 + ((chunk ^ (krow & 7)) << 4);
          ldmatrix_x4t(b[p][0], b[p][1], b[p][2], b[p][3], addr);
        }
#pragma unroll
        for (int mt = 0; mt < 2; mt++)
#pragma unroll
          for (int nt = 0; nt < 4; nt++) {
            uint32_t b0 = b[nt >> 1][(nt & 1) << 1];
            uint32_t b1 = b[nt >> 1][((nt & 1) << 1) + 1];
            mma16816(acc[mt][nt], a[mt][0], a[mt][1], a[mt][2], a[mt][3], b0, b1);
          }
      }
    }
  }

  float* C = Cp + (size_t)blockIdx.y * DD * EE;
  const int g = lane >> 2, tg = lane & 3;
#pragma unroll
  for (int mt = 0; mt < 2; mt++)
#pragma unroll
    for (int nt = 0; nt < 4; nt++) {
      int row0 = wm + mt * 16 + g;
      int col0 = n0 + wn + nt * 8 + tg * 2;
      *(float2*)(C + (size_t)row0 * ldC + col0) =
          make_float2(acc[mt][nt][0], acc[mt][nt][1]);
      *(float2*)(C + (size_t)(row0 + 8) * ldC + col0) =
          make_float2(acc[mt][nt][2], acc[mt][nt][3]);
    }

#pragma unroll
  for (int j = 0; j < 16; j++) {
#pragma unroll
    for (int o = 4; o < 32; o <<= 1)
      cnt[j] += __shfl_xor_sync(0xffffffffu, cnt[j], o);
  }
  if (lane < 4) {
#pragma unroll
    for (int j = 0; j < 16; j++)
      atomicAdd(&counts[n0 + cQ * 16 + j], cnt[j]);
  }
}

// ---------------- merged prep kernel: convT + conv_x0 + zero counts ----------
__global__ __launch_bounds__(256)
void k_prep(const float* __restrict__ T, __half* __restrict__ Th,
            const float* __restrict__ x0, __half* __restrict__ Xh,
            float* __restrict__ counts) {
  const int b = blockIdx.x;
  const int tid = threadIdx.x;
  if (b < PREP_CONVT_BLKS) {
    // --- streaming T fp32 -> fp16 ---
    size_t i = (size_t)b * 256 + tid;
    size_t n8 = (size_t)NN * NN / 8;
    const float4* src = (const float4*)T;
    uint4* dst = (uint4*)Th;
    for (size_t j = i; j < n8; j += (size_t)PREP_CONVT_BLKS * 256) {
      float4 a = src[2 * j], c = src[2 * j + 1];
      uint4 o;
      o.x = h2u(__floats2half2_rn(a.x, a.y));
      o.y = h2u(__floats2half2_rn(a.z, a.w));
      o.z = h2u(__floats2half2_rn(c.x, c.y));
      o.w = h2u(__floats2half2_rn(c.z, c.w));
      dst[j] = o;
    }
  } else if (b < PREP_CONVT_BLKS + PREP_X0_BLKS) {
    // --- x0 [N,128] fp32 -> Xh [128,N] fp16 (32x32 tile transpose) ---
    __shared__ float t[32][33];
    int bb = b - PREP_CONVT_BLKS;
    int d0 = (bb & 3) << 5;        // DD/32 = 4 tiles along d
    int n0 = (bb >> 2) << 5;       // NN/32 = 256 tiles along n
    int x = tid & 31, y = tid >> 5;  // (32, 8) layout from flat 256
#pragma unroll
    for (int i = 0; i < 32; i += 8)
      t[y + i][x] = x0[(size_t)(n0 + y + i) * DD + d0 + x];
    __syncthreads();
#pragma unroll
    for (int i = 0; i < 32; i += 8)
      Xh[(size_t)(d0 + y + i) * NN + n0 + x] = __float2half(t[x][y + i]);
  } else {
    // --- zero counts (4 blocks x 256 threads x 4 floats = 4096 = EE) ---
    int bb = b - PREP_CONVT_BLKS - PREP_X0_BLKS;
    int i = (bb * 256 + tid) * 4;
    *(float4*)(counts + i) = make_float4(0.f, 0.f, 0.f, 0.f);
  }
}

__global__ void k_final_max(const float* __restrict__ S, const float* __restrict__ counts,
                            float* __restrict__ out) {
  int d = blockIdx.x;
  const float* S0 = S + (size_t)d * EE;
  const float* S1 = S + (size_t)DD * EE + (size_t)d * EE;
  float m = -3.402823466e38f;
  for (int e = threadIdx.x; e < EE; e += blockDim.x)
    m = fmaxf(m, (S0[e] + S1[e]) / counts[e]);
#pragma unroll
  for (int o = 16; o > 0; o >>= 1) m = fmaxf(m, __shfl_xor_sync(0xffffffffu, m, o));
  __shared__ float red[4];
  int lane = threadIdx.x & 31, w = threadIdx.x >> 5;
  if (lane == 0) red[w] = m;
  __syncthreads();
  if (threadIdx.x == 0)
    out[d] = fmaxf(fmaxf(red[0], red[1]), fmaxf(red[2], red[3]));
}

// ---------------- launch ----------------
extern "C" void kernel_launch(void* const* d_in, const int* in_sizes, int n_in,
                              void* d_out, int out_size) {
  const float* x0  = (const float*)d_in[0];  // [8192,128]
  const float* T   = (const float*)d_in[1];  // [8192,8192]
  const float* gam = (const float*)d_in[2];  // [128]
  const float* bet = (const float*)d_in[3];  // [128]
  const int*   h   = (const int*)d_in[4];    // [8192,4096]
  float* out = (float*)d_out;                // [128]

  __half *Th, *Xh, *Tbh;
  float *S, *counts;
  cudaGetSymbolAddress((void**)&Th,  g_Th);
  cudaGetSymbolAddress((void**)&Xh,  g_Xh);
  cudaGetSymbolAddress((void**)&Tbh, g_Tbh);
  cudaGetSymbolAddress((void**)&S,   g_S);
  cudaGetSymbolAddress((void**)&counts, g_counts);

  cudaFuncSetAttribute(gemm_nt, cudaFuncAttributeMaxDynamicSharedMemorySize, GEMM_SMEM);
  cudaFuncSetAttribute(gemm_tn_ln, cudaFuncAttributeMaxDynamicSharedMemorySize, GEMM_SMEM);
  cudaFuncSetAttribute(gemm_tn_hcv, cudaFuncAttributeMaxDynamicSharedMemorySize, HCV_SMEM);

  // launch 1: all input prep in one partitioned-grid kernel
  k_prep<<<PREP_GRID, 256>>>(T, Th, x0, Xh, counts);

  for (int l = 0; l < 3; ++l) {  // num_layers fixed at 3 by setup_inputs
    gemm_nt<<<NN / NTILE, 256, GEMM_SMEM>>>(Xh, Th, Tbh, NN);
    gemm_tn_ln<<<NN / NTILE, 256, GEMM_SMEM>>>(Tbh, Th, NN, Xh, NN, gam, bet);
  }
  // final: sums^T = x^T @ float(h>0), h converted in-kernel, split-K=2
  gemm_tn_hcv<<<dim3(EE / NTILE, 2), 256, HCV_SMEM>>>(Xh, h, (KK / HKT) / 2, S, EE, counts);
  k_final_max<<<DD, 128>>>(S, counts, out);
}